// round 16
// baseline (speedup 1.0000x reference)
#include <cuda_runtime.h>
#include <cuda_fp16.h>
#include <math.h>

// Problem constants
#define BB   16
#define SS   257
#define SPAD 384
#define DD   1024
#define HH   16
#define DHH  64
#define FFD  4096
#define LLN  6
#define PPP  14
#define NPS  16
#define NP   256
#define KC   (3*14*14)   // 588 im2col K
#define KCP  640         // padded to 64 multiple for fp16 MMA path
#define MM   (BB*SS)     // 4112 rows
#define LNEPS 1e-5f

// ---------------- scratch ----------------------------------------------------
__device__ __half g_colh[BB*NP*KCP];              // im2col, fp16, zero-padded K
__device__ __half g_hpw [DD*KCP];                 // patch weights fp16 padded
__device__ __half g_h   [MM*DD];                  // LN output (fp16)
__device__ __half g_q16 [BB*HH*SPAD*DHH];         // head-major Q (pad rows stay 0)
__device__ __half g_k16 [BB*HH*SPAD*DHH];
__device__ __half g_v16 [BB*HH*SPAD*DHH];
__device__ __half g_ctx [MM*DD];                  // attention context (fp16)
__device__ __half g_ff  [(size_t)MM*FFD];         // MLP hidden (fp16)
// fp16 weights
__device__ __half g_hqkv[(size_t)LLN*3*DD*DD];    // [l][{q,k,v}][D][D]
__device__ float  g_bqkv[LLN*3*DD];               // packed qkv bias
__device__ __half g_ho [LLN*DD*DD];
__device__ __half g_hf1[(size_t)LLN*FFD*DD];
__device__ __half g_hf2[(size_t)LLN*FFD*DD];

__device__ __forceinline__ unsigned h2u(__half2 h) {
    unsigned u;
    __builtin_memcpy(&u, &h, 4);
    return u;
}

// ---------------- merged weight pack (all six big weight families) -----------
__global__ void k_packall(const float* __restrict__ qw, const float* __restrict__ kw,
                          const float* __restrict__ vw, const float* __restrict__ ow,
                          const float* __restrict__ f1, const float* __restrict__ f2) {
    const int nQ4 = LLN*DD*DD/4;        // float4 count per D*D family
    const int nF4 = LLN*FFD*DD/4;
    int i = blockIdx.x * blockDim.x + threadIdx.x;
    if (i < 4*nQ4) {
        int which = i / nQ4, r4 = i % nQ4;
        if (which < 3) {   // q,k,v -> interleaved g_hqkv
            const float* s = (which == 0) ? qw : (which == 1) ? kw : vw;
            int l = r4 / (DD*DD/4), rr = r4 % (DD*DD/4);
            float4 t = reinterpret_cast<const float4*>(s)[r4];
            __half2* d2 = reinterpret_cast<__half2*>(g_hqkv + ((size_t)l*3 + which)*DD*DD);
            d2[2*rr+0] = __floats2half2_rn(t.x, t.y);
            d2[2*rr+1] = __floats2half2_rn(t.z, t.w);
        } else {           // o_w -> g_ho
            float4 t = reinterpret_cast<const float4*>(ow)[r4];
            __half2* d2 = reinterpret_cast<__half2*>(g_ho);
            d2[2*r4+0] = __floats2half2_rn(t.x, t.y);
            d2[2*r4+1] = __floats2half2_rn(t.z, t.w);
        }
    } else {
        int j = i - 4*nQ4;
        if (j < nF4) {
            float4 t = reinterpret_cast<const float4*>(f1)[j];
            __half2* d2 = reinterpret_cast<__half2*>(g_hf1);
            d2[2*j+0] = __floats2half2_rn(t.x, t.y);
            d2[2*j+1] = __floats2half2_rn(t.z, t.w);
        } else {
            j -= nF4;
            if (j < nF4) {
                float4 t = reinterpret_cast<const float4*>(f2)[j];
                __half2* d2 = reinterpret_cast<__half2*>(g_hf2);
                d2[2*j+0] = __floats2half2_rn(t.x, t.y);
                d2[2*j+1] = __floats2half2_rn(t.z, t.w);
            }
        }
    }
}

__global__ void k_packb(const float* __restrict__ qb, const float* __restrict__ kb,
                        const float* __restrict__ vb) {
    int idx = blockIdx.x * blockDim.x + threadIdx.x;
    if (idx >= LLN*3*DD) return;
    int l = idx / (3*DD), r = idx % (3*DD);
    int w = r >> 10, i = r & 1023;
    const float* s = (w == 0) ? qb : (w == 1) ? kb : vb;
    g_bqkv[idx] = s[l*DD + i];
}

// pack patch_w [D][588] -> fp16 [D][640] with zero pad
__global__ void k_packpw(const float* __restrict__ s) {
    int idx = blockIdx.x * blockDim.x + threadIdx.x;
    if (idx >= DD*KCP) return;
    int row = idx / KCP, col = idx % KCP;
    g_hpw[idx] = (col < KC) ? __float2half_rn(s[row*KC + col]) : __half(0.f);
}

// ---------------- im2col (fp16, padded K) ------------------------------------
__global__ void k_im2col(const float* __restrict__ px) {
    int idx = blockIdx.x * blockDim.x + threadIdx.x;
    const int total = BB*NP*KCP;
    if (idx >= total) return;
    int kc = idx % KCP;  int bp = idx / KCP;
    if (kc >= KC) { g_colh[idx] = __half(0.f); return; }
    int p  = bp % NP;   int b  = bp / NP;
    int c  = kc / (PPP*PPP); int rem = kc % (PPP*PPP);
    int i  = rem / PPP, j = rem % PPP;
    int py = p / NPS,   pxi = p % NPS;
    int row = py*PPP + i, col = pxi*PPP + j;
    g_colh[idx] = __float2half_rn(px[((size_t)(b*3 + c)*224 + row)*224 + col]);
}

// CLS row: x[b, 0, :] = cls + pos[0]
__global__ void k_cls(const float* __restrict__ cls, const float* __restrict__ pos,
                      float* __restrict__ x) {
    int idx = blockIdx.x * blockDim.x + threadIdx.x;
    if (idx >= BB*DD) return;
    int b = idx >> 10, d = idx & 1023;
    x[(size_t)b*SS*DD + d] = cls[d] + pos[d];
}

// ================ fp16 tensor-core GEMM: C = A[M,K] * B[N,K]^T ===============
// 3-stage cp.async pipeline, CTA 128x128, BK=64, 8 warps (2x4), warp 64x32.
#define HBM 128
#define HBN 128
#define HBK 64
#define HST 16384
#define HSMEM (6*HST)      // 3 stages x (A 16KB + B 16KB)

__device__ __forceinline__ void cpa16(unsigned saddr, const void* gsrc, int bytes) {
    asm volatile("cp.async.cg.shared.global [%0], [%1], 16, %2;"
                 :: "r"(saddr), "l"(gsrc), "r"(bytes));
}
__device__ __forceinline__ void ldsm4(unsigned r[4], unsigned saddr) {
    asm volatile("ldmatrix.sync.aligned.m8n8.x4.shared.b16 {%0,%1,%2,%3}, [%4];"
                 : "=r"(r[0]), "=r"(r[1]), "=r"(r[2]), "=r"(r[3]) : "r"(saddr));
}
__device__ __forceinline__ void ldsm4t(unsigned r[4], unsigned saddr) {
    asm volatile("ldmatrix.sync.aligned.m8n8.x4.trans.shared.b16 {%0,%1,%2,%3}, [%4];"
                 : "=r"(r[0]), "=r"(r[1]), "=r"(r[2]), "=r"(r[3]) : "r"(saddr));
}
__device__ __forceinline__ void mma_f16(float c[4], const unsigned a[4],
                                        unsigned b0, unsigned b1) {
    asm volatile(
        "mma.sync.aligned.m16n8k16.row.col.f32.f16.f16.f32 "
        "{%0,%1,%2,%3}, {%4,%5,%6,%7}, {%8,%9}, {%0,%1,%2,%3};"
        : "+f"(c[0]), "+f"(c[1]), "+f"(c[2]), "+f"(c[3])
        : "r"(a[0]), "r"(a[1]), "r"(a[2]), "r"(a[3]), "r"(b0), "r"(b1));
}

// act bit0: quickGELU; bit1: store fp16; bit2: QKV head-major scatter;
// bit3: embed scatter (+pos) into x
__global__ void __launch_bounds__(256)
k_hmma(const __half* __restrict__ A, const __half* __restrict__ B,
       const float* __restrict__ bias, const float* __restrict__ add,
       void* __restrict__ Cv, int M, int N, int K, int act) {
    extern __shared__ char hsm[];
    unsigned base = (unsigned)__cvta_generic_to_shared(hsm);
    int tid = threadIdx.x;
    int lane = tid & 31, w = tid >> 5;
    int wm = w >> 2, wn = w & 3;
    int lg = lane >> 2, lt = lane & 3;
    int lr8 = lane & 7;
    int bm = blockIdx.y * HBM, bn = blockIdx.x * HBN;

    float c[4][4][4];
    #pragma unroll
    for (int i = 0; i < 4; i++)
        #pragma unroll
        for (int j = 0; j < 4; j++)
            #pragma unroll
            for (int r = 0; r < 4; r++) c[i][j][r] = 0.f;

    const int NIT = K / HBK;

    auto loadA = [&](int st, int k0) {
        #pragma unroll
        for (int t = 0; t < 4; t++) {
            int slot = tid + t*256;
            int r = slot >> 3, ch = slot & 7;
            int gr = bm + r;
            const __half* src = A + (size_t)(gr < M ? gr : 0)*K + k0 + ch*8;
            cpa16(base + st*HST + r*128u + (unsigned)((ch ^ (r & 7)) << 4),
                  src, (gr < M) ? 16 : 0);
        }
    };
    auto loadB = [&](int st, int k0) {
        #pragma unroll
        for (int t = 0; t < 4; t++) {
            int slot = tid + t*256;
            int r = slot >> 3, ch = slot & 7;
            const __half* src = B + (size_t)(bn + r)*K + k0 + ch*8;
            cpa16(base + 3*HST + st*HST + r*128u + (unsigned)((ch ^ (r & 7)) << 4),
                  src, 16);
        }
    };

    int agrp = lane >> 3;
    int arow = ((agrp & 1) << 3) + lr8;
    int akc  = agrp >> 1;
    int brow = ((lane >> 4) << 3) + lr8;
    int bkc  = (lane >> 3) & 1;

    loadA(0, 0); loadB(0, 0);
    asm volatile("cp.async.commit_group;");
    if (NIT > 1) {
        loadA(1, HBK); loadB(1, HBK);
        asm volatile("cp.async.commit_group;");
    }

    for (int it = 0; it < NIT; it++) {
        int cur = it % 3;
        if (it + 1 < NIT) asm volatile("cp.async.wait_group 1;");
        else              asm volatile("cp.async.wait_group 0;");
        __syncthreads();
        if (it + 2 < NIT) {
            int nst = (it + 2) % 3;
            loadA(nst, (it+2)*HBK);
            loadB(nst, (it+2)*HBK);
            asm volatile("cp.async.commit_group;");
        }

        unsigned aB = base + cur*HST;
        unsigned bB = base + 3*HST + cur*HST;
        #pragma unroll
        for (int ks = 0; ks < 4; ks++) {
            unsigned a[4][4], bf[2][4];
            #pragma unroll
            for (int mt = 0; mt < 4; mt++) {
                int row = wm*64 + mt*16 + arow;
                ldsm4(a[mt], aB + (unsigned)row*128u
                              + (unsigned)(((2*ks + akc) ^ lr8) << 4));
            }
            #pragma unroll
            for (int p = 0; p < 2; p++) {
                int row = wn*32 + p*16 + brow;
                ldsm4(bf[p], bB + (unsigned)row*128u
                              + (unsigned)(((2*ks + bkc) ^ lr8) << 4));
            }
            #pragma unroll
            for (int mt = 0; mt < 4; mt++)
                #pragma unroll
                for (int nt = 0; nt < 4; nt++)
                    mma_f16(c[mt][nt], a[mt],
                            bf[nt >> 1][2*(nt & 1)], bf[nt >> 1][2*(nt & 1) + 1]);
        }
    }

    // epilogue
    int which = bn >> 10;
    __half* qkvdst = (which == 0) ? g_q16 : (which == 1) ? g_k16 : g_v16;
    #pragma unroll
    for (int nt = 0; nt < 4; nt++) {
        int cn = bn + wn*32 + nt*8 + lt*2;
        float bb0 = 0.f, bb1 = 0.f;
        if (bias) { bb0 = bias[cn]; bb1 = bias[cn+1]; }
        int hcol = cn & 1023;
        int hh = hcol >> 6, dcol = hcol & 63;
        #pragma unroll
        for (int mt = 0; mt < 4; mt++) {
            #pragma unroll
            for (int h = 0; h < 2; h++) {
                int r = bm + wm*64 + mt*16 + lg + 8*h;
                if (r < M) {
                    float v0 = c[mt][nt][2*h+0] + bb0;
                    float v1 = c[mt][nt][2*h+1] + bb1;
                    if (act & 1) {
                        v0 = v0 / (1.f + __expf(-1.702f * v0));
                        v1 = v1 / (1.f + __expf(-1.702f * v1));
                    }
                    if (add && !(act & 8)) {
                        float2 t = *reinterpret_cast<const float2*>(&add[(size_t)r*N + cn]);
                        v0 += t.x; v1 += t.y;
                    }
                    if (act & 8) {
                        // embed scatter: row r -> x[b*SS + p + 1], add pos[p+1]
                        int b_ = r >> 8, p = r & 255;
                        float2 t = *reinterpret_cast<const float2*>(&add[(size_t)(p+1)*DD + cn]);
                        v0 += t.x; v1 += t.y;
                        float* Cf = (float*)Cv;
                        *reinterpret_cast<float2*>(&Cf[((size_t)(b_*SS + p + 1))*DD + cn]) =
                            make_float2(v0, v1);
                    } else if (act & 4) {
                        int b_ = r / SS, s_ = r % SS;
                        size_t di = ((size_t)(b_*HH + hh)*SPAD + s_)*64 + dcol;
                        *reinterpret_cast<__half2*>(&qkvdst[di]) =
                            __floats2half2_rn(v0, v1);
                    } else if (act & 2) {
                        __half* Ch = (__half*)Cv;
                        *reinterpret_cast<__half2*>(&Ch[(size_t)r*N + cn]) =
                            __floats2half2_rn(v0, v1);
                    } else {
                        float* Cf = (float*)Cv;
                        *reinterpret_cast<float2*>(&Cf[(size_t)r*N + cn]) =
                            make_float2(v0, v1);
                    }
                }
            }
        }
    }
}

// ================ fused flash attention (fp16 MMA, online softmax) ===========
#define FAQ 64
#define FAK 128
#define FA_SMEM (8192 + 4*16384)

__global__ void __launch_bounds__(128) k_flash() {
    extern __shared__ char fsm[];
    unsigned sm = (unsigned)__cvta_generic_to_shared(fsm);
    unsigned sQ = sm, sK0 = sm + 8192, sV0 = sm + 8192 + 32768;
    int tid = threadIdx.x, lane = tid & 31, w = tid >> 5;
    int lg = lane >> 2, lt = lane & 3, lr8 = lane & 7;
    int bh = blockIdx.y;
    int q0 = blockIdx.x * FAQ;

    const __half* qg = g_q16 + ((size_t)bh*SPAD + q0)*64;
    const __half* kg = g_k16 + (size_t)bh*SPAD*64;
    const __half* vg = g_v16 + (size_t)bh*SPAD*64;

    #pragma unroll
    for (int t = 0; t < 4; t++) {
        int slot = tid + t*128;
        int r = slot >> 3, ch = slot & 7;
        cpa16(sQ + r*128u + (unsigned)((ch ^ (r & 7)) << 4), qg + r*64 + ch*8, 16);
    }
    auto loadKV = [&](int kt, int st) {
        #pragma unroll
        for (int t = 0; t < 8; t++) {
            int slot = tid + t*128;
            int r = slot >> 3, ch = slot & 7;
            unsigned off = r*128u + (unsigned)((ch ^ (r & 7)) << 4);
            cpa16(sK0 + st*16384u + off, kg + (size_t)(kt*FAK + r)*64 + ch*8, 16);
            cpa16(sV0 + st*16384u + off, vg + (size_t)(kt*FAK + r)*64 + ch*8, 16);
        }
    };
    loadKV(0, 0);
    asm volatile("cp.async.commit_group;");
    loadKV(1, 1);
    asm volatile("cp.async.commit_group;");

    int agrp = lane >> 3;
    int arow = ((agrp & 1) << 3) + lr8;
    int akc  = agrp >> 1;
    int brow = ((lane >> 4) << 3) + lr8;
    int bkc  = (lane >> 3) & 1;
    int vrow = lr8 + ((lane >> 3) & 1) * 8;
    int vkc  = lane >> 4;

    float m_[2] = {-1e30f, -1e30f};
    float l_[2] = {0.f, 0.f};
    float o[8][4];
    #pragma unroll
    for (int i = 0; i < 8; i++)
        #pragma unroll
        for (int j = 0; j < 4; j++) o[i][j] = 0.f;

    for (int kt = 0; kt < 3; kt++) {
        int st = kt & 1;
        if (kt < 2) asm volatile("cp.async.wait_group 1;");
        else        asm volatile("cp.async.wait_group 0;");
        __syncthreads();
        unsigned sK = sK0 + st*16384u, sV = sV0 + st*16384u;

        float s[16][4];
        #pragma unroll
        for (int i = 0; i < 16; i++)
            #pragma unroll
            for (int j = 0; j < 4; j++) s[i][j] = 0.f;
        #pragma unroll
        for (int ks = 0; ks < 4; ks++) {
            unsigned a[4];
            ldsm4(a, sQ + (unsigned)(w*16 + arow)*128u
                      + (unsigned)(((2*ks + akc) ^ lr8) << 4));
            #pragma unroll
            for (int p = 0; p < 8; p++) {
                unsigned bb[4];
                ldsm4(bb, sK + (unsigned)(p*16 + brow)*128u
                          + (unsigned)(((2*ks + bkc) ^ lr8) << 4));
                mma_f16(s[2*p+0], a, bb[0], bb[1]);
                mma_f16(s[2*p+1], a, bb[2], bb[3]);
            }
        }

        unsigned ph[16][2];
        #pragma unroll
        for (int e = 0; e < 2; e++) {
            float sv[16][2];
            float mx = -1e30f;
            #pragma unroll
            for (int nt = 0; nt < 16; nt++) {
                #pragma unroll
                for (int j = 0; j < 2; j++) {
                    float v = s[nt][e*2+j] * 0.125f;
                    if (kt == 2 && (nt + lt + j) != 0) v = -1e30f;
                    sv[nt][j] = v;
                    mx = fmaxf(mx, v);
                }
            }
            mx = fmaxf(mx, __shfl_xor_sync(0xFFFFFFFF, mx, 1));
            mx = fmaxf(mx, __shfl_xor_sync(0xFFFFFFFF, mx, 2));
            float mn = fmaxf(m_[e], mx);
            float corr = __expf(m_[e] - mn);
            float rs = 0.f;
            #pragma unroll
            for (int nt = 0; nt < 16; nt++) {
                float p0 = __expf(sv[nt][0] - mn);
                float p1 = __expf(sv[nt][1] - mn);
                rs += p0 + p1;
                ph[nt][e] = h2u(__floats2half2_rn(p0, p1));
            }
            rs += __shfl_xor_sync(0xFFFFFFFF, rs, 1);
            rs += __shfl_xor_sync(0xFFFFFFFF, rs, 2);
            l_[e] = l_[e]*corr + rs;
            m_[e] = mn;
            #pragma unroll
            for (int dt = 0; dt < 8; dt++) {
                o[dt][e*2+0] *= corr;
                o[dt][e*2+1] *= corr;
            }
        }

        #pragma unroll
        for (int k2 = 0; k2 < 8; k2++) {
            unsigned a2[4] = { ph[2*k2][0], ph[2*k2][1], ph[2*k2+1][0], ph[2*k2+1][1] };
            #pragma unroll
            for (int dc = 0; dc < 4; dc++) {
                unsigned bb[4];
                ldsm4t(bb, sV + (unsigned)(k2*16 + vrow)*128u
                           + (unsigned)(((dc*2 + vkc) ^ lr8) << 4));
                mma_f16(o[2*dc+0], a2, bb[0], bb[1]);
                mma_f16(o[2*dc+1], a2, bb[2], bb[3]);
            }
        }
        __syncthreads();
        if (kt == 0) {
            loadKV(2, 0);
            asm volatile("cp.async.commit_group;");
        }
    }

    int b_ = bh >> 4, h_ = bh & 15;
    #pragma unroll
    for (int e = 0; e < 2; e++) {
        int srow = q0 + w*16 + lg + e*8;
        if (srow < SS) {
            float inv = 1.f / l_[e];
            __half* dst = g_ctx + ((size_t)(b_*SS + srow)*DD + h_*DHH);
            #pragma unroll
            for (int dt = 0; dt < 8; dt++) {
                *reinterpret_cast<__half2*>(&dst[dt*8 + lt*2]) =
                    __floats2half2_rn(o[dt][e*2+0]*inv, o[dt][e*2+1]*inv);
            }
        }
    }
}

// ---------------- LayerNorm: warp-per-row, register-resident ------------------
__global__ void __launch_bounds__(256) k_ln(const float* __restrict__ x,
                     const float* __restrict__ w,
                     const float* __restrict__ b, __half* __restrict__ out) {
    int row = blockIdx.x * 8 + (threadIdx.x >> 5);
    int lane = threadIdx.x & 31;
    const float* xr = x + (size_t)row*DD;
    float4 v[8];
    float s = 0.f;
    #pragma unroll
    for (int i = 0; i < 8; i++) {
        v[i] = *reinterpret_cast<const float4*>(&xr[(i*32 + lane)*4]);
        s += (v[i].x + v[i].y) + (v[i].z + v[i].w);
    }
    #pragma unroll
    for (int d = 16; d > 0; d >>= 1) s += __shfl_xor_sync(0xFFFFFFFF, s, d);
    float mean = s * (1.f/DD);
    float vs = 0.f;
    #pragma unroll
    for (int i = 0; i < 8; i++) {
        float d0 = v[i].x-mean, d1 = v[i].y-mean, d2 = v[i].z-mean, d3 = v[i].w-mean;
        vs += d0*d0 + d1*d1 + d2*d2 + d3*d3;
    }
    #pragma unroll
    for (int d = 16; d > 0; d >>= 1) vs += __shfl_xor_sync(0xFFFFFFFF, vs, d);
    float rstd = rsqrtf(vs * (1.f/DD) + LNEPS);
    __half* o = out + (size_t)row*DD;
    #pragma unroll
    for (int i = 0; i < 8; i++) {
        int c = (i*32 + lane)*4;
        float4 ww = *reinterpret_cast<const float4*>(&w[c]);
        float4 bb = *reinterpret_cast<const float4*>(&b[c]);
        __half2 h0 = __floats2half2_rn((v[i].x-mean)*rstd*ww.x + bb.x,
                                       (v[i].y-mean)*rstd*ww.y + bb.y);
        __half2 h1 = __floats2half2_rn((v[i].z-mean)*rstd*ww.z + bb.z,
                                       (v[i].w-mean)*rstd*ww.w + bb.w);
        uint2 pk; pk.x = h2u(h0); pk.y = h2u(h1);
        *reinterpret_cast<uint2*>(&o[c]) = pk;
    }
}

// ---------------- host orchestration ------------------------------------------
extern "C" void kernel_launch(void* const* d_in, const int* in_sizes, int n_in,
                              void* d_out, int out_size) {
    const float* pixel    = (const float*)d_in[0];
    const float* patch_w  = (const float*)d_in[1];
    const float* class_e  = (const float*)d_in[2];
    const float* pos_e    = (const float*)d_in[3];
    const float* ln1_w    = (const float*)d_in[4];
    const float* ln1_b    = (const float*)d_in[5];
    const float* q_w      = (const float*)d_in[6];
    const float* q_b      = (const float*)d_in[7];
    const float* k_w      = (const float*)d_in[8];
    const float* k_b      = (const float*)d_in[9];
    const float* v_w      = (const float*)d_in[10];
    const float* v_b      = (const float*)d_in[11];
    const float* o_w      = (const float*)d_in[12];
    const float* o_b      = (const float*)d_in[13];
    const float* ln2_w    = (const float*)d_in[14];
    const float* ln2_b    = (const float*)d_in[15];
    const float* fc1_w    = (const float*)d_in[16];
    const float* fc1_b    = (const float*)d_in[17];
    const float* fc2_w    = (const float*)d_in[18];
    const float* fc2_b    = (const float*)d_in[19];
    float* x = (float*)d_out;

    float *bqkv;
    __half *colh, *hpw, *h, *ctx, *ff, *hqkv, *ho, *hf1, *hf2;
    cudaGetSymbolAddress((void**)&colh, g_colh);
    cudaGetSymbolAddress((void**)&hpw,  g_hpw);
    cudaGetSymbolAddress((void**)&h,    g_h);
    cudaGetSymbolAddress((void**)&ctx,  g_ctx);
    cudaGetSymbolAddress((void**)&ff,   g_ff);
    cudaGetSymbolAddress((void**)&hqkv, g_hqkv);
    cudaGetSymbolAddress((void**)&bqkv, g_bqkv);
    cudaGetSymbolAddress((void**)&ho,   g_ho);
    cudaGetSymbolAddress((void**)&hf1,  g_hf1);
    cudaGetSymbolAddress((void**)&hf2,  g_hf2);

    cudaFuncSetAttribute(k_hmma,  cudaFuncAttributeMaxDynamicSharedMemorySize, HSMEM);
    cudaFuncSetAttribute(k_flash, cudaFuncAttributeMaxDynamicSharedMemorySize, FA_SMEM);

    // --- pack weights/biases (fp16), one big launch + two tiny ---
    const int nQ4 = LLN*DD*DD/4;
    const int nF4 = LLN*FFD*DD/4;
    const int nPackAll = 4*nQ4 + 2*nF4;
    k_packall<<<(nPackAll+255)/256, 256>>>(q_w, k_w, v_w, o_w, fc1_w, fc2_w);
    k_packb<<<(LLN*3*DD+255)/256, 256>>>(q_b, k_b, v_b);
    k_packpw<<<(DD*KCP+255)/256, 256>>>(patch_w);

    // --- embeddings: im2col (fp16) -> tensor GEMM (scatter + pos) + CLS row ---
    k_im2col<<<(BB*NP*KCP + 255)/256, 256>>>(pixel);
    k_hmma<<<dim3(DD/HBN, BB*NP/HBM), 256, HSMEM>>>(colh, hpw, nullptr, pos_e,
                                                    x, BB*NP, DD, KCP, 8);
    k_cls<<<(BB*DD+255)/256, 256>>>(class_e, pos_e, x);

    dim3 gQKV(3*DD/HBN, (MM + HBM-1)/HBM);   // (24, 33)
    dim3 gD  (DD/HBN,   (MM + HBM-1)/HBM);   // (8, 33)
    dim3 gFF (FFD/HBN,  (MM + HBM-1)/HBM);   // (32, 33)
    dim3 gFA (5, BB*HH);                     // flash attention

    for (int l = 0; l < LLN; l++) {
        const __half* qkvw = hqkv + (size_t)l*3*DD*DD;
        const float*  qkvb = bqkv + (size_t)l*3*DD;
        const __half* ow = ho + (size_t)l*DD*DD;   const float* ob = o_b + (size_t)l*DD;
        const __half* f1w = hf1 + (size_t)l*FFD*DD; const float* f1b = fc1_b + (size_t)l*FFD;
        const __half* f2w = hf2 + (size_t)l*FFD*DD; const float* f2b = fc2_b + (size_t)l*DD;

        // attention block
        k_ln<<<MM/8, 256>>>(x, ln1_w + (size_t)l*DD, ln1_b + (size_t)l*DD, h);
        k_hmma<<<gQKV, 256, HSMEM>>>(h, qkvw, qkvb, nullptr, nullptr,
                                     MM, 3*DD, DD, 4);            // QKV scatter
        k_flash<<<gFA, 128, FA_SMEM>>>();
        k_hmma<<<gD, 256, HSMEM>>>(ctx, ow, ob, x, x, MM, DD, DD, 0);   // +residual

        // MLP block
        k_ln<<<MM/8, 256>>>(x, ln2_w + (size_t)l*DD, ln2_b + (size_t)l*DD, h);
        k_hmma<<<gFF, 256, HSMEM>>>(h, f1w, f1b, nullptr, ff, MM, FFD, DD, 3);
        k_hmma<<<gD, 256, HSMEM>>>(ff, f2w, f2b, x, x, MM, DD, FFD, 0);

        // MoD top-k block: identity -> skipped
    }
    (void)in_sizes; (void)n_in; (void)out_size;
}

// round 17
// speedup vs baseline: 1.0159x; 1.0159x over previous
#include <cuda_runtime.h>
#include <cuda_fp16.h>
#include <math.h>

// Problem constants
#define BB   16
#define SS   257
#define SPAD 384
#define DD   1024
#define HH   16
#define DHH  64
#define FFD  4096
#define LLN  6
#define PPP  14
#define NPS  16
#define NP   256
#define KC   (3*14*14)   // 588 im2col K
#define KCP  640         // padded to 64 multiple for fp16 MMA path
#define MM   (BB*SS)     // 4112 rows
#define LNEPS 1e-5f

// ---------------- scratch ----------------------------------------------------
__device__ __half g_colh[BB*NP*KCP];              // im2col, fp16, zero-padded K
__device__ __half g_hpw [DD*KCP];                 // patch weights fp16 padded
__device__ __half g_h   [MM*DD];                  // LN output (fp16)
__device__ __half g_q16 [BB*HH*SPAD*DHH];         // head-major Q (pad rows stay 0)
__device__ __half g_k16 [BB*HH*SPAD*DHH];
__device__ __half g_v16 [BB*HH*SPAD*DHH];
__device__ __half g_ctx [MM*DD];                  // attention context (fp16)
__device__ __half g_ff  [(size_t)MM*FFD];         // MLP hidden (fp16)
// fp16 weights
__device__ __half g_hqkv[(size_t)LLN*3*DD*DD];    // [l][{q,k,v}][D][D]
__device__ float  g_bqkv[LLN*3*DD];               // packed qkv bias
__device__ __half g_ho [LLN*DD*DD];
__device__ __half g_hf1[(size_t)LLN*FFD*DD];
__device__ __half g_hf2[(size_t)LLN*FFD*DD];

__device__ __forceinline__ unsigned h2u(__half2 h) {
    unsigned u;
    __builtin_memcpy(&u, &h, 4);
    return u;
}

// ---------------- merged weight pack (all six big weight families) -----------
__global__ void k_packall(const float* __restrict__ qw, const float* __restrict__ kw,
                          const float* __restrict__ vw, const float* __restrict__ ow,
                          const float* __restrict__ f1, const float* __restrict__ f2) {
    const int nQ4 = LLN*DD*DD/4;        // float4 count per D*D family
    const int nF4 = LLN*FFD*DD/4;
    int i = blockIdx.x * blockDim.x + threadIdx.x;
    if (i < 4*nQ4) {
        int which = i / nQ4, r4 = i % nQ4;
        if (which < 3) {   // q,k,v -> interleaved g_hqkv
            const float* s = (which == 0) ? qw : (which == 1) ? kw : vw;
            int l = r4 / (DD*DD/4), rr = r4 % (DD*DD/4);
            float4 t = reinterpret_cast<const float4*>(s)[r4];
            __half2* d2 = reinterpret_cast<__half2*>(g_hqkv + ((size_t)l*3 + which)*DD*DD);
            d2[2*rr+0] = __floats2half2_rn(t.x, t.y);
            d2[2*rr+1] = __floats2half2_rn(t.z, t.w);
        } else {           // o_w -> g_ho
            float4 t = reinterpret_cast<const float4*>(ow)[r4];
            __half2* d2 = reinterpret_cast<__half2*>(g_ho);
            d2[2*r4+0] = __floats2half2_rn(t.x, t.y);
            d2[2*r4+1] = __floats2half2_rn(t.z, t.w);
        }
    } else {
        int j = i - 4*nQ4;
        if (j < nF4) {
            float4 t = reinterpret_cast<const float4*>(f1)[j];
            __half2* d2 = reinterpret_cast<__half2*>(g_hf1);
            d2[2*j+0] = __floats2half2_rn(t.x, t.y);
            d2[2*j+1] = __floats2half2_rn(t.z, t.w);
        } else {
            j -= nF4;
            if (j < nF4) {
                float4 t = reinterpret_cast<const float4*>(f2)[j];
                __half2* d2 = reinterpret_cast<__half2*>(g_hf2);
                d2[2*j+0] = __floats2half2_rn(t.x, t.y);
                d2[2*j+1] = __floats2half2_rn(t.z, t.w);
            }
        }
    }
}

__global__ void k_packb(const float* __restrict__ qb, const float* __restrict__ kb,
                        const float* __restrict__ vb) {
    int idx = blockIdx.x * blockDim.x + threadIdx.x;
    if (idx >= LLN*3*DD) return;
    int l = idx / (3*DD), r = idx % (3*DD);
    int w = r >> 10, i = r & 1023;
    const float* s = (w == 0) ? qb : (w == 1) ? kb : vb;
    g_bqkv[idx] = s[l*DD + i];
}

// pack patch_w [D][588] -> fp16 [D][640] with zero pad
__global__ void k_packpw(const float* __restrict__ s) {
    int idx = blockIdx.x * blockDim.x + threadIdx.x;
    if (idx >= DD*KCP) return;
    int row = idx / KCP, col = idx % KCP;
    g_hpw[idx] = (col < KC) ? __float2half_rn(s[row*KC + col]) : __half(0.f);
}

// ---------------- im2col (fp16, padded K) ------------------------------------
__global__ void k_im2col(const float* __restrict__ px) {
    int idx = blockIdx.x * blockDim.x + threadIdx.x;
    const int total = BB*NP*KCP;
    if (idx >= total) return;
    int kc = idx % KCP;  int bp = idx / KCP;
    if (kc >= KC) { g_colh[idx] = __half(0.f); return; }
    int p  = bp % NP;   int b  = bp / NP;
    int c  = kc / (PPP*PPP); int rem = kc % (PPP*PPP);
    int i  = rem / PPP, j = rem % PPP;
    int py = p / NPS,   pxi = p % NPS;
    int row = py*PPP + i, col = pxi*PPP + j;
    g_colh[idx] = __float2half_rn(px[((size_t)(b*3 + c)*224 + row)*224 + col]);
}

// CLS row: x[b, 0, :] = cls + pos[0]
__global__ void k_cls(const float* __restrict__ cls, const float* __restrict__ pos,
                      float* __restrict__ x) {
    int idx = blockIdx.x * blockDim.x + threadIdx.x;
    if (idx >= BB*DD) return;
    int b = idx >> 10, d = idx & 1023;
    x[(size_t)b*SS*DD + d] = cls[d] + pos[d];
}

// ================ fp16 tensor-core GEMM: C = A[M,K] * B[N,K]^T ===============
// 2-stage cp.async pipeline (64 KB smem -> 3 CTA/SM), CTA 128x128, BK=64.
#define HBM 128
#define HBN 128
#define HBK 64
#define HST 16384
#define HSMEM (4*HST)

__device__ __forceinline__ void cpa16(unsigned saddr, const void* gsrc, int bytes) {
    asm volatile("cp.async.cg.shared.global [%0], [%1], 16, %2;"
                 :: "r"(saddr), "l"(gsrc), "r"(bytes));
}
__device__ __forceinline__ void ldsm4(unsigned r[4], unsigned saddr) {
    asm volatile("ldmatrix.sync.aligned.m8n8.x4.shared.b16 {%0,%1,%2,%3}, [%4];"
                 : "=r"(r[0]), "=r"(r[1]), "=r"(r[2]), "=r"(r[3]) : "r"(saddr));
}
__device__ __forceinline__ void ldsm4t(unsigned r[4], unsigned saddr) {
    asm volatile("ldmatrix.sync.aligned.m8n8.x4.trans.shared.b16 {%0,%1,%2,%3}, [%4];"
                 : "=r"(r[0]), "=r"(r[1]), "=r"(r[2]), "=r"(r[3]) : "r"(saddr));
}
__device__ __forceinline__ void mma_f16(float c[4], const unsigned a[4],
                                        unsigned b0, unsigned b1) {
    asm volatile(
        "mma.sync.aligned.m16n8k16.row.col.f32.f16.f16.f32 "
        "{%0,%1,%2,%3}, {%4,%5,%6,%7}, {%8,%9}, {%0,%1,%2,%3};"
        : "+f"(c[0]), "+f"(c[1]), "+f"(c[2]), "+f"(c[3])
        : "r"(a[0]), "r"(a[1]), "r"(a[2]), "r"(a[3]), "r"(b0), "r"(b1));
}

// act bit0: quickGELU; bit1: store fp16; bit2: QKV head-major scatter;
// bit3: embed scatter (+pos) into x
__global__ void __launch_bounds__(256)
k_hmma(const __half* __restrict__ A, const __half* __restrict__ B,
       const float* __restrict__ bias, const float* __restrict__ add,
       void* __restrict__ Cv, int M, int N, int K, int act) {
    extern __shared__ char hsm[];
    unsigned base = (unsigned)__cvta_generic_to_shared(hsm);
    int tid = threadIdx.x;
    int lane = tid & 31, w = tid >> 5;
    int wm = w >> 2, wn = w & 3;
    int lg = lane >> 2, lt = lane & 3;
    int lr8 = lane & 7;
    int bm = blockIdx.y * HBM, bn = blockIdx.x * HBN;

    float c[4][4][4];
    #pragma unroll
    for (int i = 0; i < 4; i++)
        #pragma unroll
        for (int j = 0; j < 4; j++)
            #pragma unroll
            for (int r = 0; r < 4; r++) c[i][j][r] = 0.f;

    const int NIT = K / HBK;

    auto loadA = [&](int st, int k0) {
        #pragma unroll
        for (int t = 0; t < 4; t++) {
            int slot = tid + t*256;
            int r = slot >> 3, ch = slot & 7;
            int gr = bm + r;
            const __half* src = A + (size_t)(gr < M ? gr : 0)*K + k0 + ch*8;
            cpa16(base + st*HST + r*128u + (unsigned)((ch ^ (r & 7)) << 4),
                  src, (gr < M) ? 16 : 0);
        }
    };
    auto loadB = [&](int st, int k0) {
        #pragma unroll
        for (int t = 0; t < 4; t++) {
            int slot = tid + t*256;
            int r = slot >> 3, ch = slot & 7;
            const __half* src = B + (size_t)(bn + r)*K + k0 + ch*8;
            cpa16(base + 2*HST + st*HST + r*128u + (unsigned)((ch ^ (r & 7)) << 4),
                  src, 16);
        }
    };

    int agrp = lane >> 3;
    int arow = ((agrp & 1) << 3) + lr8;
    int akc  = agrp >> 1;
    int brow = ((lane >> 4) << 3) + lr8;
    int bkc  = (lane >> 3) & 1;

    loadA(0, 0); loadB(0, 0);
    asm volatile("cp.async.commit_group;");

    for (int it = 0; it < NIT; it++) {
        int cur = it & 1;
        if (it + 1 < NIT) {
            loadA(cur ^ 1, (it+1)*HBK);
            loadB(cur ^ 1, (it+1)*HBK);
            asm volatile("cp.async.commit_group;");
            asm volatile("cp.async.wait_group 1;");
        } else {
            asm volatile("cp.async.wait_group 0;");
        }
        __syncthreads();

        unsigned aB = base + cur*HST;
        unsigned bB = base + 2*HST + cur*HST;
        #pragma unroll
        for (int ks = 0; ks < 4; ks++) {
            unsigned a[4][4], bf[2][4];
            #pragma unroll
            for (int mt = 0; mt < 4; mt++) {
                int row = wm*64 + mt*16 + arow;
                ldsm4(a[mt], aB + (unsigned)row*128u
                              + (unsigned)(((2*ks + akc) ^ lr8) << 4));
            }
            #pragma unroll
            for (int p = 0; p < 2; p++) {
                int row = wn*32 + p*16 + brow;
                ldsm4(bf[p], bB + (unsigned)row*128u
                              + (unsigned)(((2*ks + bkc) ^ lr8) << 4));
            }
            #pragma unroll
            for (int mt = 0; mt < 4; mt++)
                #pragma unroll
                for (int nt = 0; nt < 4; nt++)
                    mma_f16(c[mt][nt], a[mt],
                            bf[nt >> 1][2*(nt & 1)], bf[nt >> 1][2*(nt & 1) + 1]);
        }
        __syncthreads();
    }

    // epilogue
    int which = bn >> 10;
    __half* qkvdst = (which == 0) ? g_q16 : (which == 1) ? g_k16 : g_v16;
    #pragma unroll
    for (int nt = 0; nt < 4; nt++) {
        int cn = bn + wn*32 + nt*8 + lt*2;
        float bb0 = 0.f, bb1 = 0.f;
        if (bias) { bb0 = bias[cn]; bb1 = bias[cn+1]; }
        int hcol = cn & 1023;
        int hh = hcol >> 6, dcol = hcol & 63;
        #pragma unroll
        for (int mt = 0; mt < 4; mt++) {
            #pragma unroll
            for (int h = 0; h < 2; h++) {
                int r = bm + wm*64 + mt*16 + lg + 8*h;
                if (r < M) {
                    float v0 = c[mt][nt][2*h+0] + bb0;
                    float v1 = c[mt][nt][2*h+1] + bb1;
                    if (act & 1) {
                        v0 = v0 / (1.f + __expf(-1.702f * v0));
                        v1 = v1 / (1.f + __expf(-1.702f * v1));
                    }
                    if (add && !(act & 8)) {
                        float2 t = *reinterpret_cast<const float2*>(&add[(size_t)r*N + cn]);
                        v0 += t.x; v1 += t.y;
                    }
                    if (act & 8) {
                        // embed scatter: row r -> x[b*SS + p + 1], add pos[p+1]
                        int b_ = r >> 8, p = r & 255;
                        float2 t = *reinterpret_cast<const float2*>(&add[(size_t)(p+1)*DD + cn]);
                        v0 += t.x; v1 += t.y;
                        float* Cf = (float*)Cv;
                        *reinterpret_cast<float2*>(&Cf[((size_t)(b_*SS + p + 1))*DD + cn]) =
                            make_float2(v0, v1);
                    } else if (act & 4) {
                        int b_ = r / SS, s_ = r % SS;
                        size_t di = ((size_t)(b_*HH + hh)*SPAD + s_)*64 + dcol;
                        *reinterpret_cast<__half2*>(&qkvdst[di]) =
                            __floats2half2_rn(v0, v1);
                    } else if (act & 2) {
                        __half* Ch = (__half*)Cv;
                        *reinterpret_cast<__half2*>(&Ch[(size_t)r*N + cn]) =
                            __floats2half2_rn(v0, v1);
                    } else {
                        float* Cf = (float*)Cv;
                        *reinterpret_cast<float2*>(&Cf[(size_t)r*N + cn]) =
                            make_float2(v0, v1);
                    }
                }
            }
        }
    }
}

// ================ fused flash attention (fp16 MMA, online softmax) ===========
#define FAQ 64
#define FAK 128
#define FA_SMEM (8192 + 4*16384)

__global__ void __launch_bounds__(128) k_flash() {
    extern __shared__ char fsm[];
    unsigned sm = (unsigned)__cvta_generic_to_shared(fsm);
    unsigned sQ = sm, sK0 = sm + 8192, sV0 = sm + 8192 + 32768;
    int tid = threadIdx.x, lane = tid & 31, w = tid >> 5;
    int lg = lane >> 2, lt = lane & 3, lr8 = lane & 7;
    int bh = blockIdx.y;
    int q0 = blockIdx.x * FAQ;

    const __half* qg = g_q16 + ((size_t)bh*SPAD + q0)*64;
    const __half* kg = g_k16 + (size_t)bh*SPAD*64;
    const __half* vg = g_v16 + (size_t)bh*SPAD*64;

    #pragma unroll
    for (int t = 0; t < 4; t++) {
        int slot = tid + t*128;
        int r = slot >> 3, ch = slot & 7;
        cpa16(sQ + r*128u + (unsigned)((ch ^ (r & 7)) << 4), qg + r*64 + ch*8, 16);
    }
    auto loadKV = [&](int kt, int st) {
        #pragma unroll
        for (int t = 0; t < 8; t++) {
            int slot = tid + t*128;
            int r = slot >> 3, ch = slot & 7;
            unsigned off = r*128u + (unsigned)((ch ^ (r & 7)) << 4);
            cpa16(sK0 + st*16384u + off, kg + (size_t)(kt*FAK + r)*64 + ch*8, 16);
            cpa16(sV0 + st*16384u + off, vg + (size_t)(kt*FAK + r)*64 + ch*8, 16);
        }
    };
    loadKV(0, 0);
    asm volatile("cp.async.commit_group;");
    loadKV(1, 1);
    asm volatile("cp.async.commit_group;");

    int agrp = lane >> 3;
    int arow = ((agrp & 1) << 3) + lr8;
    int akc  = agrp >> 1;
    int brow = ((lane >> 4) << 3) + lr8;
    int bkc  = (lane >> 3) & 1;
    int vrow = lr8 + ((lane >> 3) & 1) * 8;
    int vkc  = lane >> 4;

    float m_[2] = {-1e30f, -1e30f};
    float l_[2] = {0.f, 0.f};
    float o[8][4];
    #pragma unroll
    for (int i = 0; i < 8; i++)
        #pragma unroll
        for (int j = 0; j < 4; j++) o[i][j] = 0.f;

    for (int kt = 0; kt < 3; kt++) {
        int st = kt & 1;
        if (kt < 2) asm volatile("cp.async.wait_group 1;");
        else        asm volatile("cp.async.wait_group 0;");
        __syncthreads();
        unsigned sK = sK0 + st*16384u, sV = sV0 + st*16384u;

        float s[16][4];
        #pragma unroll
        for (int i = 0; i < 16; i++)
            #pragma unroll
            for (int j = 0; j < 4; j++) s[i][j] = 0.f;
        #pragma unroll
        for (int ks = 0; ks < 4; ks++) {
            unsigned a[4];
            ldsm4(a, sQ + (unsigned)(w*16 + arow)*128u
                      + (unsigned)(((2*ks + akc) ^ lr8) << 4));
            #pragma unroll
            for (int p = 0; p < 8; p++) {
                unsigned bb[4];
                ldsm4(bb, sK + (unsigned)(p*16 + brow)*128u
                          + (unsigned)(((2*ks + bkc) ^ lr8) << 4));
                mma_f16(s[2*p+0], a, bb[0], bb[1]);
                mma_f16(s[2*p+1], a, bb[2], bb[3]);
            }
        }

        unsigned ph[16][2];
        #pragma unroll
        for (int e = 0; e < 2; e++) {
            float sv[16][2];
            float mx = -1e30f;
            #pragma unroll
            for (int nt = 0; nt < 16; nt++) {
                #pragma unroll
                for (int j = 0; j < 2; j++) {
                    float v = s[nt][e*2+j] * 0.125f;
                    if (kt == 2 && (nt + lt + j) != 0) v = -1e30f;
                    sv[nt][j] = v;
                    mx = fmaxf(mx, v);
                }
            }
            mx = fmaxf(mx, __shfl_xor_sync(0xFFFFFFFF, mx, 1));
            mx = fmaxf(mx, __shfl_xor_sync(0xFFFFFFFF, mx, 2));
            float mn = fmaxf(m_[e], mx);
            float corr = __expf(m_[e] - mn);
            float rs = 0.f;
            #pragma unroll
            for (int nt = 0; nt < 16; nt++) {
                float p0 = __expf(sv[nt][0] - mn);
                float p1 = __expf(sv[nt][1] - mn);
                rs += p0 + p1;
                ph[nt][e] = h2u(__floats2half2_rn(p0, p1));
            }
            rs += __shfl_xor_sync(0xFFFFFFFF, rs, 1);
            rs += __shfl_xor_sync(0xFFFFFFFF, rs, 2);
            l_[e] = l_[e]*corr + rs;
            m_[e] = mn;
            #pragma unroll
            for (int dt = 0; dt < 8; dt++) {
                o[dt][e*2+0] *= corr;
                o[dt][e*2+1] *= corr;
            }
        }

        #pragma unroll
        for (int k2 = 0; k2 < 8; k2++) {
            unsigned a2[4] = { ph[2*k2][0], ph[2*k2][1], ph[2*k2+1][0], ph[2*k2+1][1] };
            #pragma unroll
            for (int dc = 0; dc < 4; dc++) {
                unsigned bb[4];
                ldsm4t(bb, sV + (unsigned)(k2*16 + vrow)*128u
                           + (unsigned)(((dc*2 + vkc) ^ lr8) << 4));
                mma_f16(o[2*dc+0], a2, bb[0], bb[1]);
                mma_f16(o[2*dc+1], a2, bb[2], bb[3]);
            }
        }
        __syncthreads();
        if (kt == 0) {
            loadKV(2, 0);
            asm volatile("cp.async.commit_group;");
        }
    }

    int b_ = bh >> 4, h_ = bh & 15;
    #pragma unroll
    for (int e = 0; e < 2; e++) {
        int srow = q0 + w*16 + lg + e*8;
        if (srow < SS) {
            float inv = 1.f / l_[e];
            __half* dst = g_ctx + ((size_t)(b_*SS + srow)*DD + h_*DHH);
            #pragma unroll
            for (int dt = 0; dt < 8; dt++) {
                *reinterpret_cast<__half2*>(&dst[dt*8 + lt*2]) =
                    __floats2half2_rn(o[dt][e*2+0]*inv, o[dt][e*2+1]*inv);
            }
        }
    }
}

// ---------------- LayerNorm: warp-per-row, register-resident ------------------
__global__ void __launch_bounds__(256) k_ln(const float* __restrict__ x,
                     const float* __restrict__ w,
                     const float* __restrict__ b, __half* __restrict__ out) {
    int row = blockIdx.x * 8 + (threadIdx.x >> 5);
    int lane = threadIdx.x & 31;
    const float* xr = x + (size_t)row*DD;
    float4 v[8];
    float s = 0.f;
    #pragma unroll
    for (int i = 0; i < 8; i++) {
        v[i] = *reinterpret_cast<const float4*>(&xr[(i*32 + lane)*4]);
        s += (v[i].x + v[i].y) + (v[i].z + v[i].w);
    }
    #pragma unroll
    for (int d = 16; d > 0; d >>= 1) s += __shfl_xor_sync(0xFFFFFFFF, s, d);
    float mean = s * (1.f/DD);
    float vs = 0.f;
    #pragma unroll
    for (int i = 0; i < 8; i++) {
        float d0 = v[i].x-mean, d1 = v[i].y-mean, d2 = v[i].z-mean, d3 = v[i].w-mean;
        vs += d0*d0 + d1*d1 + d2*d2 + d3*d3;
    }
    #pragma unroll
    for (int d = 16; d > 0; d >>= 1) vs += __shfl_xor_sync(0xFFFFFFFF, vs, d);
    float rstd = rsqrtf(vs * (1.f/DD) + LNEPS);
    __half* o = out + (size_t)row*DD;
    #pragma unroll
    for (int i = 0; i < 8; i++) {
        int c = (i*32 + lane)*4;
        float4 ww = *reinterpret_cast<const float4*>(&w[c]);
        float4 bb = *reinterpret_cast<const float4*>(&b[c]);
        __half2 h0 = __floats2half2_rn((v[i].x-mean)*rstd*ww.x + bb.x,
                                       (v[i].y-mean)*rstd*ww.y + bb.y);
        __half2 h1 = __floats2half2_rn((v[i].z-mean)*rstd*ww.z + bb.z,
                                       (v[i].w-mean)*rstd*ww.w + bb.w);
        uint2 pk; pk.x = h2u(h0); pk.y = h2u(h1);
        *reinterpret_cast<uint2*>(&o[c]) = pk;
    }
}

// ---------------- host orchestration ------------------------------------------
extern "C" void kernel_launch(void* const* d_in, const int* in_sizes, int n_in,
                              void* d_out, int out_size) {
    const float* pixel    = (const float*)d_in[0];
    const float* patch_w  = (const float*)d_in[1];
    const float* class_e  = (const float*)d_in[2];
    const float* pos_e    = (const float*)d_in[3];
    const float* ln1_w    = (const float*)d_in[4];
    const float* ln1_b    = (const float*)d_in[5];
    const float* q_w      = (const float*)d_in[6];
    const float* q_b      = (const float*)d_in[7];
    const float* k_w      = (const float*)d_in[8];
    const float* k_b      = (const float*)d_in[9];
    const float* v_w      = (const float*)d_in[10];
    const float* v_b      = (const float*)d_in[11];
    const float* o_w      = (const float*)d_in[12];
    const float* o_b      = (const float*)d_in[13];
    const float* ln2_w    = (const float*)d_in[14];
    const float* ln2_b    = (const float*)d_in[15];
    const float* fc1_w    = (const float*)d_in[16];
    const float* fc1_b    = (const float*)d_in[17];
    const float* fc2_w    = (const float*)d_in[18];
    const float* fc2_b    = (const float*)d_in[19];
    float* x = (float*)d_out;

    float *bqkv;
    __half *colh, *hpw, *h, *ctx, *ff, *hqkv, *ho, *hf1, *hf2;
    cudaGetSymbolAddress((void**)&colh, g_colh);
    cudaGetSymbolAddress((void**)&hpw,  g_hpw);
    cudaGetSymbolAddress((void**)&h,    g_h);
    cudaGetSymbolAddress((void**)&ctx,  g_ctx);
    cudaGetSymbolAddress((void**)&ff,   g_ff);
    cudaGetSymbolAddress((void**)&hqkv, g_hqkv);
    cudaGetSymbolAddress((void**)&bqkv, g_bqkv);
    cudaGetSymbolAddress((void**)&ho,   g_ho);
    cudaGetSymbolAddress((void**)&hf1,  g_hf1);
    cudaGetSymbolAddress((void**)&hf2,  g_hf2);

    cudaFuncSetAttribute(k_hmma,  cudaFuncAttributeMaxDynamicSharedMemorySize, HSMEM);
    cudaFuncSetAttribute(k_flash, cudaFuncAttributeMaxDynamicSharedMemorySize, FA_SMEM);

    // --- pack weights/biases (fp16), one big launch + two tiny ---
    const int nQ4 = LLN*DD*DD/4;
    const int nF4 = LLN*FFD*DD/4;
    const int nPackAll = 4*nQ4 + 2*nF4;
    k_packall<<<(nPackAll+255)/256, 256>>>(q_w, k_w, v_w, o_w, fc1_w, fc2_w);
    k_packb<<<(LLN*3*DD+255)/256, 256>>>(q_b, k_b, v_b);
    k_packpw<<<(DD*KCP+255)/256, 256>>>(patch_w);

    // --- embeddings: im2col (fp16) -> tensor GEMM (scatter + pos) + CLS row ---
    k_im2col<<<(BB*NP*KCP + 255)/256, 256>>>(pixel);
    k_hmma<<<dim3(DD/HBN, BB*NP/HBM), 256, HSMEM>>>(colh, hpw, nullptr, pos_e,
                                                    x, BB*NP, DD, KCP, 8);
    k_cls<<<(BB*DD+255)/256, 256>>>(class_e, pos_e, x);

    dim3 gQKV(3*DD/HBN, (MM + HBM-1)/HBM);   // (24, 33)
    dim3 gD  (DD/HBN,   (MM + HBM-1)/HBM);   // (8, 33)
    dim3 gFF (FFD/HBN,  (MM + HBM-1)/HBM);   // (32, 33)
    dim3 gFA (5, BB*HH);                     // flash attention

    for (int l = 0; l < LLN; l++) {
        const __half* qkvw = hqkv + (size_t)l*3*DD*DD;
        const float*  qkvb = bqkv + (size_t)l*3*DD;
        const __half* ow = ho + (size_t)l*DD*DD;   const float* ob = o_b + (size_t)l*DD;
        const __half* f1w = hf1 + (size_t)l*FFD*DD; const float* f1b = fc1_b + (size_t)l*FFD;
        const __half* f2w = hf2 + (size_t)l*FFD*DD; const float* f2b = fc2_b + (size_t)l*DD;

        // attention block
        k_ln<<<MM/8, 256>>>(x, ln1_w + (size_t)l*DD, ln1_b + (size_t)l*DD, h);
        k_hmma<<<gQKV, 256, HSMEM>>>(h, qkvw, qkvb, nullptr, nullptr,
                                     MM, 3*DD, DD, 4);            // QKV scatter
        k_flash<<<gFA, 128, FA_SMEM>>>();
        k_hmma<<<gD, 256, HSMEM>>>(ctx, ow, ob, x, x, MM, DD, DD, 0);   // +residual

        // MLP block
        k_ln<<<MM/8, 256>>>(x, ln2_w + (size_t)l*DD, ln2_b + (size_t)l*DD, h);
        k_hmma<<<gFF, 256, HSMEM>>>(h, f1w, f1b, nullptr, ff, MM, FFD, DD, 3);
        k_hmma<<<gD, 256, HSMEM>>>(ff, f2w, f2b, x, x, MM, DD, FFD, 0);

        // MoD top-k block: identity -> skipped
    }
    (void)in_sizes; (void)n_in; (void)out_size;
}